// round 9
// baseline (speedup 1.0000x reference)
#include <cuda_runtime.h>

// Problem constants
#define HW 4096            // 64*64
#define CIN 128
#define NOFF 18            // 2*K2
#define KD 1152            // CIN*9

// Scratch (device globals; no allocation allowed)
__device__ float g_h[8 * 128 * HW];        // BN+ReLU output, 16 MB
__device__ float g_off1[8 * NOFF * HW];    // conv_offsets
__device__ float g_off2[8 * NOFF * HW];    // dconv_offsets
__device__ unsigned g_wt2[KD * 128];       // dc_w tap-major tf32 [k2*128+c][oc]
__device__ unsigned g_wtA2[2 * KD * 24];   // off_w tap-major tf32 hi|lo planes
__device__ unsigned g_wtB2[2 * KD * 24];   // odc_w tap-major tf32 hi|lo planes

// ---------------------------------------------------------------------------
// K1: BN + ReLU (vectorized float4).
// ---------------------------------------------------------------------------
__global__ void k_bnrelu(const float* __restrict__ x,
                         const float* __restrict__ gamma,
                         const float* __restrict__ beta,
                         const float* __restrict__ mean,
                         const float* __restrict__ var) {
    int i = blockIdx.x * blockDim.x + threadIdx.x;
    int c = (i >> 10) & 127;
    float s = rsqrtf(var[c] + 1e-5f) * gamma[c];
    float m = mean[c], bt = beta[c];
    float4 v = ((const float4*)x)[i];
    v.x = fmaxf((v.x - m) * s + bt, 0.f);
    v.y = fmaxf((v.y - m) * s + bt, 0.f);
    v.z = fmaxf((v.z - m) * s + bt, 0.f);
    v.w = fmaxf((v.w - m) * s + bt, 0.f);
    ((float4*)g_h)[i] = v;
}

// ---------------------------------------------------------------------------
// K0a: dc_w [oc][c*9+k2] -> g_wt2 tap-major tf32 [k2*128+c][oc].
// ---------------------------------------------------------------------------
__global__ void k_transpose_wt(const float* __restrict__ w) {
    int i = blockIdx.x * blockDim.x + threadIdx.x;   // 147456
    int oc = i & 127, jp = i >> 7;
    int k2 = jp >> 7, c = jp & 127;
    float v = w[oc * KD + c * 9 + k2];
    unsigned t;
    asm("cvt.rna.tf32.f32 %0, %1;" : "=r"(t) : "f"(v));
    g_wt2[i] = t;
}

// K0b: 18-oc weight [18][KD] -> tap-major tf32 hi/lo planes [k2*128+c][24].
// Plane 0 (offset 0): hi. Plane 1 (offset KD*24): lo = tf32(v - float(hi)).
__global__ void k_transpose_w18t(const float* __restrict__ w,
                                 unsigned* __restrict__ dst) {
    int i = blockIdx.x * blockDim.x + threadIdx.x;   // KD*24 = 27648
    if (i >= KD * 24) return;
    int j = i / 24, oc = i - j * 24;
    int k2 = j >> 7, c = j & 127;
    float v = (oc < NOFF) ? w[oc * KD + c * 9 + k2] : 0.f;
    unsigned hi, lo;
    asm("cvt.rna.tf32.f32 %0, %1;" : "=r"(hi) : "f"(v));
    float r = v - __uint_as_float(hi);
    asm("cvt.rna.tf32.f32 %0, %1;" : "=r"(lo) : "f"(r));
    dst[i] = hi;
    dst[i + KD * 24] = lo;
}

__device__ __forceinline__ void mma_tf32(float* d, const unsigned* a,
                                         unsigned b0, unsigned b1) {
    asm volatile(
        "mma.sync.aligned.m16n8k8.row.col.f32.tf32.tf32.f32 "
        "{%0,%1,%2,%3}, {%4,%5,%6,%7}, {%8,%9}, {%0,%1,%2,%3};"
        : "+f"(d[0]), "+f"(d[1]), "+f"(d[2]), "+f"(d[3])
        : "r"(a[0]), "r"(a[1]), "r"(a[2]), "r"(a[3]), "r"(b0), "r"(b1));
}

// ---------------------------------------------------------------------------
// Shared bilinear-setup helper (PX pixels x 9 taps into s_wq/s_iq).
// ---------------------------------------------------------------------------
template<int PX>
__device__ __forceinline__ void bilin_setup(
        const float* off, int b, int y, int x0, int tid,
        float4* s_wq, short4* s_iq) {
    for (int t = tid; t < PX * 9; t += 128) {
        int px = t & (PX - 1), k2 = t / PX;
        int x = x0 + px;
        float py, pxf;
        if (off) {
            const float* offp = off + b * NOFF * HW + y * 64 + x;
            py  = (float)(y - 1 + k2 / 3) + offp[(2 * k2) * HW];
            pxf = (float)(x - 1 + k2 % 3) + offp[(2 * k2 + 1) * HW];
        } else {
            py  = (float)(y - 1 + k2 / 3);
            pxf = (float)(x - 1 + k2 % 3);
        }
        float fy0 = floorf(py), fx0 = floorf(pxf);
        float wy1 = py - fy0, wx1 = pxf - fx0;
        float wy0 = 1.f - wy1, wx0 = 1.f - wx1;
        int iy0 = (int)fy0, ix0 = (int)fx0;
        int iy1 = iy0 + 1, ix1 = ix0 + 1;
        bool vy0 = ((unsigned)iy0 < 64u), vy1 = ((unsigned)iy1 < 64u);
        bool vx0 = ((unsigned)ix0 < 64u), vx1 = ((unsigned)ix1 < 64u);
        float4 w;
        w.x = (vy0 && vx0) ? wy0 * wx0 : 0.f;
        w.y = (vy0 && vx1) ? wy0 * wx1 : 0.f;
        w.z = (vy1 && vx0) ? wy1 * wx0 : 0.f;
        w.w = (vy1 && vx1) ? wy1 * wx1 : 0.f;
        int cy0 = min(max(iy0, 0), 63), cy1 = min(max(iy1, 0), 63);
        int cx0 = min(max(ix0, 0), 63), cx1 = min(max(ix1, 0), 63);
        s_wq[t] = w;
        s_iq[t] = make_short4((short)(cy0 * 64 + cx0), (short)(cy0 * 64 + cx1),
                              (short)(cy1 * 64 + cx0), (short)(cy1 * 64 + cx1));
    }
}

// ---------------------------------------------------------------------------
// K2/K3: 18-oc (deformable) conv — tf32x3 error-compensated GEMM.
// Tile 64px x 24oc (18 real). 128 thr, 4 warps (warp 16px x 24oc). Grid 512.
// acc += a_hi*b_hi + a_lo*b_hi + a_hi*b_lo  (~fp32 precision).
// ---------------------------------------------------------------------------
__global__ void __launch_bounds__(128) k_gemm18(
        const float* __restrict__ off,      // [b][18][HW] or nullptr
        const unsigned* __restrict__ wB,    // hi plane; lo at +KD*24
        const float* __restrict__ bias,
        float* __restrict__ out) {
    __shared__ float4   s_wq[576];
    __shared__ short4   s_iq[576];
    __shared__ unsigned s_ah[32][72];   // A hi, pad 72 (==8 mod 32)
    __shared__ unsigned s_al[32][72];   // A lo
    __shared__ unsigned s_bh[32][40];   // B hi, pad 40
    __shared__ unsigned s_bl[32][40];   // B lo

    int tid = threadIdx.x;
    int blk = blockIdx.x;               // b*64 + y
    int b = blk >> 6, y = blk & 63;

    bilin_setup<64>(off, b, y, 0, tid, s_wq, s_iq);
    __syncthreads();

    int lane = tid & 31, warp = tid >> 5;
    int pxw = warp * 16;
    int gid = lane >> 2, tig = lane & 3;

    float acc[3][4];
#pragma unroll
    for (int nt = 0; nt < 3; nt++)
#pragma unroll
        for (int q = 0; q < 4; q++) acc[nt][q] = 0.f;

    int px_s = tid & 63, cl0 = (tid >> 6) * 16;   // 16 samples/thread
    const float* hb = g_h + (b << 7) * HW;

    for (int kc = 0; kc < 36; kc++) {
        // Stage B hi/lo (32 x 24 each)
        {
            const unsigned* sh = wB + kc * 768;
            const unsigned* sl = sh + KD * 24;
            for (int i = tid; i < 768; i += 128) {
                int r = i / 24, c = i - r * 24;
                s_bh[r][c] = sh[i];
                s_bl[r][c] = sl[i];
            }
        }
        // Sample A tile: 64px x 32ch; hi/lo split at fill
        {
            int k2 = kc >> 2, c0 = (kc & 3) * 32;
            float4 w = s_wq[k2 * 64 + px_s];
            short4 ixs = s_iq[k2 * 64 + px_s];
            int i0 = ixs.x, i1 = ixs.y, i2 = ixs.z, i3 = ixs.w;
            const float* hp = hb + (c0 + cl0) * HW;
#pragma unroll
            for (int i = 0; i < 16; i++, hp += HW) {
                float v = 0.f;
                if (w.x != 0.f) v  = w.x * hp[i0];
                if (w.y != 0.f) v += w.y * hp[i1];
                if (w.z != 0.f) v += w.z * hp[i2];
                if (w.w != 0.f) v += w.w * hp[i3];
                unsigned hi, lo;
                asm("cvt.rna.tf32.f32 %0, %1;" : "=r"(hi) : "f"(v));
                float r = v - __uint_as_float(hi);
                asm("cvt.rna.tf32.f32 %0, %1;" : "=r"(lo) : "f"(r));
                s_ah[cl0 + i][px_s] = hi;
                s_al[cl0 + i][px_s] = lo;
            }
        }
        __syncthreads();

#pragma unroll
        for (int k0 = 0; k0 < 32; k0 += 8) {
            unsigned ah[4], al[4];
            ah[0] = s_ah[k0 + tig][pxw + gid];
            ah[1] = s_ah[k0 + tig][pxw + gid + 8];
            ah[2] = s_ah[k0 + tig + 4][pxw + gid];
            ah[3] = s_ah[k0 + tig + 4][pxw + gid + 8];
            al[0] = s_al[k0 + tig][pxw + gid];
            al[1] = s_al[k0 + tig][pxw + gid + 8];
            al[2] = s_al[k0 + tig + 4][pxw + gid];
            al[3] = s_al[k0 + tig + 4][pxw + gid + 8];
#pragma unroll
            for (int nt = 0; nt < 3; nt++) {
                unsigned bh0 = s_bh[k0 + tig][nt * 8 + gid];
                unsigned bh1 = s_bh[k0 + tig + 4][nt * 8 + gid];
                unsigned bl0 = s_bl[k0 + tig][nt * 8 + gid];
                unsigned bl1 = s_bl[k0 + tig + 4][nt * 8 + gid];
                mma_tf32(acc[nt], ah, bh0, bh1);
                mma_tf32(acc[nt], al, bh0, bh1);
                mma_tf32(acc[nt], ah, bl0, bl1);
            }
        }
        __syncthreads();
    }

    // Epilogue (skip pad cols >= 18)
    int obase = b * NOFF * HW + y * 64;
#pragma unroll
    for (int nt = 0; nt < 3; nt++) {
        int oc0 = nt * 8 + 2 * tig;
        if (oc0 < NOFF) {
            float bs0 = bias[oc0], bs1 = bias[oc0 + 1];
            int px0 = pxw + gid;
            out[obase + oc0 * HW + px0]           = acc[nt][0] + bs0;
            out[obase + (oc0 + 1) * HW + px0]     = acc[nt][1] + bs1;
            out[obase + oc0 * HW + px0 + 8]       = acc[nt][2] + bs0;
            out[obase + (oc0 + 1) * HW + px0 + 8] = acc[nt][3] + bs1;
        }
    }
}

// ---------------------------------------------------------------------------
// K4: 128-oc deformable conv — single-pass tf32 GEMM (R8 BIG, unchanged).
// Tile 32px x 128oc, 128 thr (warp 32px x 32oc), grid 1024.
// ---------------------------------------------------------------------------
__global__ void __launch_bounds__(128) k_gemm128(
        const float* __restrict__ off,
        const unsigned* __restrict__ wB,
        const float* __restrict__ bias,
        float* __restrict__ out) {
    __shared__ float4   s_wq[288];
    __shared__ short4   s_iq[288];
    __shared__ unsigned s_a[32][40];    // pad 40
    __shared__ unsigned s_b[32][136];   // pad 136

    int tid = threadIdx.x;
    int blk = blockIdx.x;
    int row = blk >> 1;
    int b = row >> 6, y = row & 63, x0 = (blk & 1) * 32;

    bilin_setup<32>(off, b, y, x0, tid, s_wq, s_iq);
    __syncthreads();

    int lane = tid & 31, warp = tid >> 5;
    int ocw = warp * 32;
    int gid = lane >> 2, tig = lane & 3;

    float acc[2][4][4];
#pragma unroll
    for (int mt = 0; mt < 2; mt++)
#pragma unroll
        for (int nt = 0; nt < 4; nt++)
#pragma unroll
            for (int q = 0; q < 4; q++) acc[mt][nt][q] = 0.f;

    int px_s = tid & 31, cl0 = (tid >> 5) * 8;   // 8 samples/thread
    const float* hb = g_h + (b << 7) * HW;

    for (int kc = 0; kc < 36; kc++) {
        {
            const uint4* src = (const uint4*)wB + kc * 1024;
            for (int i = tid; i < 1024; i += 128) {
                uint4 v = src[i];
                *(uint4*)&s_b[i >> 5][(i & 31) * 4] = v;
            }
        }
        {
            int k2 = kc >> 2, c0 = (kc & 3) * 32;
            float4 w = s_wq[k2 * 32 + px_s];
            short4 ixs = s_iq[k2 * 32 + px_s];
            int i0 = ixs.x, i1 = ixs.y, i2 = ixs.z, i3 = ixs.w;
            const float* hp = hb + (c0 + cl0) * HW;
#pragma unroll
            for (int i = 0; i < 8; i++, hp += HW) {
                float v = w.x * hp[i0] + w.y * hp[i1]
                        + w.z * hp[i2] + w.w * hp[i3];
                unsigned t32;
                asm("cvt.rna.tf32.f32 %0, %1;" : "=r"(t32) : "f"(v));
                s_a[cl0 + i][px_s] = t32;
            }
        }
        __syncthreads();

#pragma unroll
        for (int k0 = 0; k0 < 32; k0 += 8) {
            unsigned a[2][4];
#pragma unroll
            for (int mt = 0; mt < 2; mt++) {
                int pxb = mt * 16;
                a[mt][0] = s_a[k0 + tig][pxb + gid];
                a[mt][1] = s_a[k0 + tig][pxb + gid + 8];
                a[mt][2] = s_a[k0 + tig + 4][pxb + gid];
                a[mt][3] = s_a[k0 + tig + 4][pxb + gid + 8];
            }
#pragma unroll
            for (int nt = 0; nt < 4; nt++) {
                unsigned b0 = s_b[k0 + tig][ocw + nt * 8 + gid];
                unsigned b1 = s_b[k0 + tig + 4][ocw + nt * 8 + gid];
                mma_tf32(acc[0][nt], a[0], b0, b1);
                mma_tf32(acc[1][nt], a[1], b0, b1);
            }
        }
        __syncthreads();
    }

    int obase = (b << 7) * HW + y * 64 + x0;
#pragma unroll
    for (int nt = 0; nt < 4; nt++) {
        int oc0 = ocw + nt * 8 + 2 * tig;
        float bs0 = bias[oc0], bs1 = bias[oc0 + 1];
#pragma unroll
        for (int mt = 0; mt < 2; mt++) {
            int px0 = mt * 16 + gid;
            out[obase + oc0 * HW + px0]           = acc[mt][nt][0] + bs0;
            out[obase + (oc0 + 1) * HW + px0]     = acc[mt][nt][1] + bs1;
            out[obase + oc0 * HW + px0 + 8]       = acc[mt][nt][2] + bs0;
            out[obase + (oc0 + 1) * HW + px0 + 8] = acc[mt][nt][3] + bs1;
        }
    }
}

// ---------------------------------------------------------------------------
// Launch. Position 4 (profiled) = k_gemm18 conv flavor.
// Input order: x, bn_gamma, bn_beta, bn_mean, bn_var,
// off_w, off_b, odc_w, odc_b, dc_w, dc_b. Output: float32 [8,128,64,64].
// ---------------------------------------------------------------------------
extern "C" void kernel_launch(void* const* d_in, const int* in_sizes, int n_in,
                              void* d_out, int out_size) {
    const float* x     = (const float*)d_in[0];
    const float* gamma = (const float*)d_in[1];
    const float* beta  = (const float*)d_in[2];
    const float* mean  = (const float*)d_in[3];
    const float* var   = (const float*)d_in[4];
    const float* off_w = (const float*)d_in[5];
    const float* off_b = (const float*)d_in[6];
    const float* odc_w = (const float*)d_in[7];
    const float* odc_b = (const float*)d_in[8];
    const float* dc_w  = (const float*)d_in[9];
    const float* dc_b  = (const float*)d_in[10];
    float* out = (float*)d_out;

    unsigned *wtA2, *wtB2, *wt2;
    float *off1, *off2;
    cudaGetSymbolAddress((void**)&wtA2, g_wtA2);
    cudaGetSymbolAddress((void**)&wtB2, g_wtB2);
    cudaGetSymbolAddress((void**)&wt2,  g_wt2);
    cudaGetSymbolAddress((void**)&off1, g_off1);
    cudaGetSymbolAddress((void**)&off2, g_off2);

    k_transpose_w18t<<<108, 256>>>(off_w, wtA2);               // 1
    k_bnrelu<<<4096, 256>>>(x, gamma, beta, mean, var);        // 2
    k_transpose_w18t<<<108, 256>>>(odc_w, wtB2);               // 3
    k_gemm18<<<512, 128>>>(nullptr, wtA2, off_b, off1);        // 4 <- profiled
    k_gemm18<<<512, 128>>>(off1, wtB2, odc_b, off2);           // 5
    k_transpose_wt<<<576, 256>>>(dc_w);                        // 6
    k_gemm128<<<1024, 128>>>(off2, wt2, dc_b, out);            // 7
}

// round 10
// speedup vs baseline: 1.4111x; 1.4111x over previous
#include <cuda_runtime.h>

// Problem constants
#define HW 4096            // 64*64
#define CIN 128
#define NOFF 18            // 2*K2
#define KD 1152            // CIN*9
#define NELEM (8 * 128 * HW)
#define PCH (8 * NOFF * HW)   // per-chunk partial stride = 589824

// Scratch (device globals; no allocation allowed)
__device__ float  g_h[NELEM];          // BN+ReLU output, 16 MB
__device__ float2 g_hp[NELEM];         // (h[x], h[x+1]) pairs, 32 MB
__device__ float  g_part[8 * PCH];     // conv18 partials (8 chunks), 18.9 MB
__device__ float  g_part2[8 * PCH];    // dconv18 partials
__device__ unsigned g_wt2[KD * 128];   // dc_w tap-major tf32 [k2*128+c][oc]
__device__ float  g_wtA[KD * NOFF];    // off_w transposed [c*9+k2][18]
__device__ float  g_wtB[KD * NOFF];    // odc_w transposed

// ---------------------------------------------------------------------------
// K1: BN + ReLU; writes both scalar g_h and pair g_hp.
// ---------------------------------------------------------------------------
__global__ void k_bnrelu(const float* __restrict__ x,
                         const float* __restrict__ gamma,
                         const float* __restrict__ beta,
                         const float* __restrict__ mean,
                         const float* __restrict__ var) {
    int i = blockIdx.x * blockDim.x + threadIdx.x;   // float4 index
    int c = (i >> 10) & 127;
    float s = rsqrtf(var[c] + 1e-5f) * gamma[c];
    float m = mean[c], bt = beta[c];
    float4 v = ((const float4*)x)[i];
    v.x = fmaxf((v.x - m) * s + bt, 0.f);
    v.y = fmaxf((v.y - m) * s + bt, 0.f);
    v.z = fmaxf((v.z - m) * s + bt, 0.f);
    v.w = fmaxf((v.w - m) * s + bt, 0.f);
    ((float4*)g_h)[i] = v;
    // next element (first of following float4), BN'd with ITS channel params
    float nx = 0.f;
    int e = i * 4 + 4;
    if (e < NELEM) {
        int c2 = (e >> 12) & 127;
        float s2 = rsqrtf(var[c2] + 1e-5f) * gamma[c2];
        nx = fmaxf((x[e] - mean[c2]) * s2 + beta[c2], 0.f);
    }
    float4 p0 = make_float4(v.x, v.y, v.y, v.z);
    float4 p1 = make_float4(v.z, v.w, v.w, nx);
    ((float4*)g_hp)[i * 2]     = p0;
    ((float4*)g_hp)[i * 2 + 1] = p1;
}

// ---------------------------------------------------------------------------
// K0a: dc_w [oc][c*9+k2] -> g_wt2 tap-major tf32 [k2*128+c][oc].
// ---------------------------------------------------------------------------
__global__ void k_transpose_wt(const float* __restrict__ w) {
    int i = blockIdx.x * blockDim.x + threadIdx.x;   // 147456
    int oc = i & 127, jp = i >> 7;
    int k2 = jp >> 7, c = jp & 127;
    float v = w[oc * KD + c * 9 + k2];
    unsigned t;
    asm("cvt.rna.tf32.f32 %0, %1;" : "=r"(t) : "f"(v));
    g_wt2[i] = t;
}

// K0b: both 18-oc weights [18][KD] -> [KD][18] fp32, in one launch.
__global__ void k_transpose_w18x2(const float* __restrict__ wA,
                                  const float* __restrict__ wB) {
    int i = blockIdx.x * blockDim.x + threadIdx.x;   // 2*KD*18 = 41472
    if (i >= 2 * KD * NOFF) return;
    int which = i >= KD * NOFF;
    int r = which ? i - KD * NOFF : i;
    int j = r / NOFF, oc = r - j * NOFF;
    const float* w = which ? wB : wA;
    float* dst = which ? g_wtB : g_wtA;
    dst[r] = w[oc * KD + j];
}

// ---------------------------------------------------------------------------
// Bilinear decomposition -> pair-gather params.
// Returns e0,e1 (x-pair weights), wy0,wy1 (row weights, validity-zeroed),
// o0,o1 (flat pair indices). Matches torchvision zero-OOB semantics.
// ---------------------------------------------------------------------------
__device__ __forceinline__ void bilin_pair(
        float py, float px,
        float& e0, float& e1, float& wy0e, float& wy1e, int& o0, int& o1) {
    float fy0 = floorf(py), fx0 = floorf(px);
    float wy1 = py - fy0, wx1 = px - fx0;
    float wy0 = 1.f - wy1, wx0 = 1.f - wx1;
    int iy0 = (int)fy0, ix0 = (int)fx0;
    bool vy0 = ((unsigned)iy0 < 64u), vy1 = ((unsigned)(iy0 + 1) < 64u);
    bool vx0 = ((unsigned)ix0 < 64u), vx1 = ((unsigned)(ix0 + 1) < 64u);
    wy0e = vy0 ? wy0 : 0.f;
    wy1e = vy1 ? wy1 : 0.f;
    int xb;
    if (vx0)      { xb = ix0; e0 = wx0; e1 = vx1 ? wx1 : 0.f; }
    else if (vx1) { xb = 0;   e0 = wx1; e1 = 0.f; }   // ix0 == -1
    else          { xb = 0;   e0 = 0.f; e1 = 0.f; }
    int y0c = min(max(iy0, 0), 63), y1c = min(max(iy0 + 1, 0), 63);
    o0 = y0c * 64 + xb;
    o1 = y1c * 64 + xb;
}

// ---------------------------------------------------------------------------
// K2/K3: 18-oc (deformable) conv, 8-way channel split (16 ch/chunk).
// Grid (256, 8), 128 thr = 2 rows. partIn==nullptr -> plain conv (g_h).
// Deform: offsets = obias + sum of 8 conv partials (read inline);
//         samples via g_hp float2 pairs (2x LDG.64 per sample).
// ---------------------------------------------------------------------------
__global__ void __launch_bounds__(128) k_dc18v2(
        const float* __restrict__ partIn,   // offset partials or nullptr
        const float* __restrict__ obias,    // offset conv bias (deform only)
        const float* __restrict__ wtT,      // [KD][18] fp32
        float* __restrict__ partOut) {
    __shared__ float ws[16 * 9 * NOFF];     // 10368 B
    int tid = threadIdx.x;
    int row = blockIdx.x * 2 + (tid >> 6);
    int b = row >> 6, y = row & 63, x = tid & 63;
    int chunk = blockIdx.y;                 // 0..7
    int c0 = chunk * 16;

    const float* wsrc = wtT + c0 * 9 * NOFF;
    for (int i = tid; i < 16 * 9 * NOFF; i += 128) ws[i] = wsrc[i];
    __syncthreads();

    float acc[NOFF];
#pragma unroll
    for (int o = 0; o < NOFF; o++) acc[o] = 0.f;

    if (partIn) {
        const float2* hb2 = (const float2*)g_hp + ((b << 7) + c0) * HW;
        int obase = b * NOFF * HW + y * 64 + x;
        for (int k2 = 0; k2 < 9; k2++) {
            float dy = obias[2 * k2], dx = obias[2 * k2 + 1];
            int oy = obase + (2 * k2) * HW, ox = oy + HW;
#pragma unroll
            for (int k = 0; k < 8; k++) {
                dy += partIn[k * PCH + oy];
                dx += partIn[k * PCH + ox];
            }
            float py = (float)(y - 1 + k2 / 3) + dy;
            float px = (float)(x - 1 + k2 % 3) + dx;
            float e0, e1, wy0, wy1; int o0, o1;
            bilin_pair(py, px, e0, e1, wy0, wy1, o0, o1);

            const float2* hp = hb2;
            for (int cl = 0; cl < 16; cl++, hp += HW) {
                float2 q0 = hp[o0], q1 = hp[o1];
                float s = e0 * (wy0 * q0.x + wy1 * q1.x)
                        + e1 * (wy0 * q0.y + wy1 * q1.y);
                const float* wr = ws + (cl * 9 + k2) * NOFF;
#pragma unroll
                for (int op = 0; op < 9; op++) {
                    float2 w = *(const float2*)&wr[2 * op];
                    acc[2 * op]     = fmaf(s, w.x, acc[2 * op]);
                    acc[2 * op + 1] = fmaf(s, w.y, acc[2 * op + 1]);
                }
            }
        }
    } else {
        const float* hb = g_h + ((b << 7) + c0) * HW;
        for (int k2 = 0; k2 < 9; k2++) {
            int yy = y - 1 + k2 / 3, xx = x - 1 + k2 % 3;
            bool v = ((unsigned)yy < 64u) && ((unsigned)xx < 64u);
            int idx = v ? (yy * 64 + xx) : 0;
            const float* hp = hb;
            for (int cl = 0; cl < 16; cl++, hp += HW) {
                float s = v ? hp[idx] : 0.f;
                const float* wr = ws + (cl * 9 + k2) * NOFF;
#pragma unroll
                for (int op = 0; op < 9; op++) {
                    float2 w = *(const float2*)&wr[2 * op];
                    acc[2 * op]     = fmaf(s, w.x, acc[2 * op]);
                    acc[2 * op + 1] = fmaf(s, w.y, acc[2 * op + 1]);
                }
            }
        }
    }

    float* dst = partOut + chunk * PCH + b * NOFF * HW + y * 64 + x;
#pragma unroll
    for (int o = 0; o < NOFF; o++) dst[o * HW] = acc[o];
}

// ---------------------------------------------------------------------------
// K4: 128-oc deformable conv — tf32 mma GEMM (R6 structure), 256 thr,
// static smem 38 KB, 3 blocks/SM. Offsets from g_part2 sum + odc_b inline.
// Samples via g_hp pairs.
// ---------------------------------------------------------------------------
__device__ __forceinline__ void mma_tf32(float* d, const unsigned* a,
                                         unsigned b0, unsigned b1) {
    asm volatile(
        "mma.sync.aligned.m16n8k8.row.col.f32.tf32.tf32.f32 "
        "{%0,%1,%2,%3}, {%4,%5,%6,%7}, {%8,%9}, {%0,%1,%2,%3};"
        : "+f"(d[0]), "+f"(d[1]), "+f"(d[2]), "+f"(d[3])
        : "r"(a[0]), "r"(a[1]), "r"(a[2]), "r"(a[3]), "r"(b0), "r"(b1));
}

__global__ void __launch_bounds__(256, 3) k_dconv128_mma(
        const float* __restrict__ obias,    // odc_b (offset bias)
        const float* __restrict__ bias,     // dc_b
        float* __restrict__ out) {
    __shared__ float4   s_e[576];       // e0,e1,wy0,wy1 per (tap,px)
    __shared__ short2   s_o[576];       // o0,o1
    __shared__ unsigned s_a[32][72];    // tf32 A tile, pad 72
    __shared__ unsigned s_b[32][136];   // tf32 B tile, pad 136

    int tid = threadIdx.x;
    int row = blockIdx.x;               // b*64 + y
    int b = row >> 6, y = row & 63;

    // Phase 0: offsets (8-partial sum + bias) -> bilinear tables
    for (int t = tid; t < 576; t += 256) {
        int px = t & 63, k2 = t >> 6;
        int obase = b * NOFF * HW + y * 64 + px;
        float dy = obias[2 * k2], dx = obias[2 * k2 + 1];
        int oy = obase + (2 * k2) * HW, ox = oy + HW;
#pragma unroll
        for (int k = 0; k < 8; k++) {
            dy += g_part2[k * PCH + oy];
            dx += g_part2[k * PCH + ox];
        }
        float py  = (float)(y - 1 + k2 / 3) + dy;
        float pxf = (float)(px - 1 + k2 % 3) + dx;
        float e0, e1, wy0, wy1; int o0, o1;
        bilin_pair(py, pxf, e0, e1, wy0, wy1, o0, o1);
        s_e[t] = make_float4(e0, e1, wy0, wy1);
        s_o[t] = make_short2((short)o0, (short)o1);
    }
    __syncthreads();

    int lane = tid & 31, warp = tid >> 5;
    int pxw = (warp & 1) * 32;
    int ocw = (warp >> 1) * 32;
    int gid = lane >> 2, tig = lane & 3;

    float acc[2][4][4];
#pragma unroll
    for (int mt = 0; mt < 2; mt++)
#pragma unroll
        for (int nt = 0; nt < 4; nt++)
#pragma unroll
            for (int q = 0; q < 4; q++) acc[mt][nt][q] = 0.f;

    int px_s = tid & 63, cl0 = (tid >> 6) * 8;   // 8 samples/thread
    const float2* hb2 = (const float2*)g_hp + (b << 7) * HW;

    for (int kc = 0; kc < 36; kc++) {
        // Stage B tile
        {
            const uint4* src = (const uint4*)g_wt2 + kc * 1024;
            for (int i = tid; i < 1024; i += 256) {
                uint4 v = src[i];
                *(uint4*)&s_b[i >> 5][(i & 31) * 4] = v;
            }
        }
        // Sample A tile via pairs
        {
            int k2 = kc >> 2, c0 = (kc & 3) * 32;
            float4 ew = s_e[k2 * 64 + px_s];
            short2 oo = s_o[k2 * 64 + px_s];
            int o0 = oo.x, o1 = oo.y;
            const float2* hp = hb2 + (c0 + cl0) * HW;
#pragma unroll
            for (int i = 0; i < 8; i++, hp += HW) {
                float2 q0 = hp[o0], q1 = hp[o1];
                float v = ew.x * (ew.z * q0.x + ew.w * q1.x)
                        + ew.y * (ew.z * q0.y + ew.w * q1.y);
                unsigned t32;
                asm("cvt.rna.tf32.f32 %0, %1;" : "=r"(t32) : "f"(v));
                s_a[cl0 + i][px_s] = t32;
            }
        }
        __syncthreads();

#pragma unroll
        for (int k0 = 0; k0 < 32; k0 += 8) {
            unsigned a[2][4];
#pragma unroll
            for (int mt = 0; mt < 2; mt++) {
                int pxb = pxw + mt * 16;
                a[mt][0] = s_a[k0 + tig][pxb + gid];
                a[mt][1] = s_a[k0 + tig][pxb + gid + 8];
                a[mt][2] = s_a[k0 + tig + 4][pxb + gid];
                a[mt][3] = s_a[k0 + tig + 4][pxb + gid + 8];
            }
#pragma unroll
            for (int nt = 0; nt < 4; nt++) {
                unsigned b0 = s_b[k0 + tig][ocw + nt * 8 + gid];
                unsigned b1 = s_b[k0 + tig + 4][ocw + nt * 8 + gid];
                mma_tf32(acc[0][nt], a[0], b0, b1);
                mma_tf32(acc[1][nt], a[1], b0, b1);
            }
        }
        __syncthreads();
    }

    int obase2 = (b << 7) * HW + y * 64;
#pragma unroll
    for (int nt = 0; nt < 4; nt++) {
        int oc0 = ocw + nt * 8 + 2 * tig;
        float bs0 = bias[oc0], bs1 = bias[oc0 + 1];
#pragma unroll
        for (int mt = 0; mt < 2; mt++) {
            int px0 = pxw + mt * 16 + gid;
            out[obase2 + oc0 * HW + px0]           = acc[mt][nt][0] + bs0;
            out[obase2 + (oc0 + 1) * HW + px0]     = acc[mt][nt][1] + bs1;
            out[obase2 + oc0 * HW + px0 + 8]       = acc[mt][nt][2] + bs0;
            out[obase2 + (oc0 + 1) * HW + px0 + 8] = acc[mt][nt][3] + bs1;
        }
    }
}

// ---------------------------------------------------------------------------
// Launch. Index 3 (profiled) = deform k_dc18v2.
// Input order: x, bn_gamma, bn_beta, bn_mean, bn_var,
// off_w, off_b, odc_w, odc_b, dc_w, dc_b. Output: float32 [8,128,64,64].
// ---------------------------------------------------------------------------
extern "C" void kernel_launch(void* const* d_in, const int* in_sizes, int n_in,
                              void* d_out, int out_size) {
    const float* x     = (const float*)d_in[0];
    const float* gamma = (const float*)d_in[1];
    const float* beta  = (const float*)d_in[2];
    const float* mean  = (const float*)d_in[3];
    const float* var   = (const float*)d_in[4];
    const float* off_w = (const float*)d_in[5];
    const float* off_b = (const float*)d_in[6];
    const float* odc_w = (const float*)d_in[7];
    const float* odc_b = (const float*)d_in[8];
    const float* dc_w  = (const float*)d_in[9];
    const float* dc_b  = (const float*)d_in[10];
    float* out = (float*)d_out;

    float *wtA, *wtB, *part, *part2;
    cudaGetSymbolAddress((void**)&wtA,   g_wtA);
    cudaGetSymbolAddress((void**)&wtB,   g_wtB);
    cudaGetSymbolAddress((void**)&part,  g_part);
    cudaGetSymbolAddress((void**)&part2, g_part2);

    k_transpose_w18x2<<<162, 256>>>(off_w, odc_w);                     // 0
    k_bnrelu<<<4096, 256>>>(x, gamma, beta, mean, var);                // 1
    k_dc18v2<<<dim3(256, 8), 128>>>(nullptr, nullptr, wtA, part);      // 2
    k_dc18v2<<<dim3(256, 8), 128>>>(part, off_b, wtB, part2);          // 3 <- prof
    k_transpose_wt<<<576, 256>>>(dc_w);                                // 4
    k_dconv128_mma<<<512, 256>>>(odc_b, dc_b, out);                    // 5
}